// round 7
// baseline (speedup 1.0000x reference)
#include <cuda_runtime.h>
#include <cuda_fp16.h>
#include <math.h>

#define NMAX 50000
#define EMAX 800000
#define DDIM 64

#define SBLK 1024                          // nodes per scan block
#define NSB ((NMAX + SBLK - 1) / SBLK)     // 49

// scratch (all zero-initialized at module load)
__device__ float  g_h[(size_t)NMAX * DDIM];    // fp32 transformed features (self/skip)
__device__ __half g_hh[(size_t)NMAX * DDIM];   // fp16 copy (neighbor gather)
__device__ int    g_cnt[NMAX];                 // per-node degree (zeroed by gather)
__device__ int    g_off[NMAX];                 // CSR offsets
__device__ int    g_fill[NMAX];                // fill cursors
__device__ unsigned long long g_aggf[NSB];     // packed (flag<<32 | blocksum), reset by fill
__device__ uint2  g_edges[EMAX];               // (src, w-bits) grouped by dst

// ---------------------------------------------------------------------------
// Kernel 1: h = X @ W^T (fp32 + fp16 stores) + fused degree histogram.
// 128 rows x 64 cols per block, 8x4 register tile per thread.
// ---------------------------------------------------------------------------
#define XSTR 132
#define WSTR 68
#define GBLKS ((NMAX + 127) / 128)   // 391

__global__ void __launch_bounds__(256) gemm_kernel(
    const float* __restrict__ X, const float* __restrict__ W,
    const int* __restrict__ edst, int E, int n)
{
    __shared__ float sW[DDIM * WSTR];   // sW[d*WSTR + o]
    __shared__ float sX[DDIM * XSTR];   // sX[d*XSTR + r]

    const int tid  = threadIdx.x;
    const int row0 = blockIdx.x * 128;

    // fused histogram: grid-stride, fire-and-forget reductions (g_cnt is zero
    // at launch start: static init on first run, re-zeroed by gather_kernel).
    for (int i = blockIdx.x * 256 + tid; i < E; i += GBLKS * 256)
        atomicAdd(&g_cnt[edst[i]], 1);

    #pragma unroll
    for (int i = 0; i < 16; i++) {
        int idx = tid + i * 256;
        int o = idx >> 6, d = idx & 63;
        sW[d * WSTR + o] = W[idx];
    }
    #pragma unroll
    for (int i = 0; i < 32; i++) {
        int idx = tid + i * 256;
        int r = idx >> 6, d = idx & 63;
        int gr = row0 + r;
        sX[d * XSTR + r] = (gr < n) ? X[(size_t)gr * DDIM + d] : 0.0f;
    }
    __syncthreads();

    const int tx = tid & 15;
    const int ty = tid >> 4;
    const int o0 = tx * 4;
    const int r0 = ty * 8;

    float acc[8][4];
    #pragma unroll
    for (int i = 0; i < 8; i++)
        #pragma unroll
        for (int j = 0; j < 4; j++) acc[i][j] = 0.0f;

    #pragma unroll 16
    for (int d = 0; d < DDIM; d++) {
        float4 xa = *reinterpret_cast<const float4*>(&sX[d * XSTR + r0]);
        float4 xb = *reinterpret_cast<const float4*>(&sX[d * XSTR + r0 + 4]);
        float4 wv = *reinterpret_cast<const float4*>(&sW[d * WSTR + o0]);
        float x[8] = {xa.x, xa.y, xa.z, xa.w, xb.x, xb.y, xb.z, xb.w};
        float w[4] = {wv.x, wv.y, wv.z, wv.w};
        #pragma unroll
        for (int i = 0; i < 8; i++)
            #pragma unroll
            for (int j = 0; j < 4; j++)
                acc[i][j] = fmaf(x[i], w[j], acc[i][j]);
    }

    #pragma unroll
    for (int i = 0; i < 8; i++) {
        int gr = row0 + r0 + i;
        if (gr < n) {
            float4 hv = make_float4(acc[i][0], acc[i][1], acc[i][2], acc[i][3]);
            *reinterpret_cast<float4*>(&g_h[(size_t)gr * DDIM + o0]) = hv;
            // fp16 copy: two half2 stores (4-byte aligned since o0 % 4 == 0)
            __half2* dst2 = reinterpret_cast<__half2*>(&g_hh[(size_t)gr * DDIM + o0]);
            dst2[0] = __float22half2_rn(make_float2(hv.x, hv.y));
            dst2[1] = __float22half2_rn(make_float2(hv.z, hv.w));
        }
    }
}

// ---------------------------------------------------------------------------
// Kernel 2: single-pass exclusive scan of g_cnt -> g_off / g_fill.
// 49 blocks; each publishes its aggregate as (1<<32 | sum) in one 64-bit word
// (value+flag atomic together -> no fence ordering needed), then sums all
// lower-indexed aggregates. All 49 blocks fit in wave 1 -> spin is safe.
// ---------------------------------------------------------------------------
__global__ void __launch_bounds__(256) scan_kernel(int n)
{
    __shared__ int sv[256];
    __shared__ int sbase;
    const int b = blockIdx.x, t = threadIdx.x;
    const int base = b * SBLK + t * 4;

    int c[4];
    int s = 0;
    #pragma unroll
    for (int k = 0; k < 4; k++) {
        int i = base + k;
        c[k] = (i < n) ? g_cnt[i] : 0;
        s += c[k];
    }
    sv[t] = s;
    if (t == 0) sbase = 0;
    __syncthreads();
    #pragma unroll
    for (int off = 1; off < 256; off <<= 1) {
        int u = (t >= off) ? sv[t - off] : 0;
        __syncthreads();
        sv[t] += u;
        __syncthreads();
    }

    if (t == 0) {
        unsigned long long v = (1ULL << 32) | (unsigned)sv[255];
        atomicExch(&g_aggf[b], v);
    }
    __syncthreads();

    if (t < b) {
        unsigned long long v;
        do {
            v = *((volatile unsigned long long*)&g_aggf[t]);
        } while (!(v >> 32));
        atomicAdd(&sbase, (int)(unsigned)v);
    }
    __syncthreads();

    int run = sbase + sv[t] - s;   // global exclusive prefix
    #pragma unroll
    for (int k = 0; k < 4; k++) {
        int i = base + k;
        if (i < n) {
            g_off[i]  = run;
            g_fill[i] = run;
            run += c[k];
        }
    }
}

// ---------------------------------------------------------------------------
// Kernel 3: fill CSR edge array; also reset scan flags for the next replay.
// ---------------------------------------------------------------------------
__global__ void fill_kernel(const int* __restrict__ src,
                            const int* __restrict__ dst,
                            const float* __restrict__ ew, int E)
{
    int i = blockIdx.x * blockDim.x + threadIdx.x;
    if (i < NSB) g_aggf[i] = 0ULL;   // scan already consumed these
    if (i < E) {
        int d = dst[i];
        int slot = atomicAdd(&g_fill[d], 1);
        g_edges[slot] = make_uint2((unsigned)src[i], __float_as_uint(ew[i]));
    }
}

// ---------------------------------------------------------------------------
// Kernel 4: per-node gather (fp16 neighbors) + fp32 skip + bias + SELU.
// One warp per node; lane owns 2 columns. Resets g_cnt for next replay.
// ---------------------------------------------------------------------------
__global__ void __launch_bounds__(512) gather_kernel(
    const float* __restrict__ bias,
    const float* __restrict__ skipw,
    float* __restrict__ out, int n)
{
    const int lane = threadIdx.x & 31;
    const int node = blockIdx.x * 16 + (threadIdx.x >> 5);
    if (node >= n) return;

    const int start = g_off[node];
    const int deg   = g_cnt[node];
    const int end   = start + deg;
    if (lane == 0) g_cnt[node] = 0;   // restore zero invariant for next run

    const __half2* hh2 = reinterpret_cast<const __half2*>(g_hh);

    float2 acc = make_float2(0.0f, 0.0f);

    int e = start;
    for (; e + 4 <= end; e += 4) {
        uint2 m0 = __ldg(&g_edges[e]);
        uint2 m1 = __ldg(&g_edges[e + 1]);
        uint2 m2 = __ldg(&g_edges[e + 2]);
        uint2 m3 = __ldg(&g_edges[e + 3]);
        float2 h0 = __half22float2(hh2[(size_t)m0.x * 32 + lane]);
        float2 h1 = __half22float2(hh2[(size_t)m1.x * 32 + lane]);
        float2 h2 = __half22float2(hh2[(size_t)m2.x * 32 + lane]);
        float2 h3 = __half22float2(hh2[(size_t)m3.x * 32 + lane]);
        float w0 = __uint_as_float(m0.y);
        float w1 = __uint_as_float(m1.y);
        float w2 = __uint_as_float(m2.y);
        float w3 = __uint_as_float(m3.y);
        acc.x = fmaf(w0, h0.x, acc.x); acc.y = fmaf(w0, h0.y, acc.y);
        acc.x = fmaf(w1, h1.x, acc.x); acc.y = fmaf(w1, h1.y, acc.y);
        acc.x = fmaf(w2, h2.x, acc.x); acc.y = fmaf(w2, h2.y, acc.y);
        acc.x = fmaf(w3, h3.x, acc.x); acc.y = fmaf(w3, h3.y, acc.y);
    }
    for (; e < end; e++) {
        uint2 m = __ldg(&g_edges[e]);
        float2 hv = __half22float2(hh2[(size_t)m.x * 32 + lane]);
        float w = __uint_as_float(m.y);
        acc.x = fmaf(w, hv.x, acc.x);
        acc.y = fmaf(w, hv.y, acc.y);
    }

    const int col = lane * 2;
    const float2 hself = *reinterpret_cast<const float2*>(&g_h[(size_t)node * DDIM + col]);
    const float2 sw = *reinterpret_cast<const float2*>(&skipw[col]);
    const float2 bv = *reinterpret_cast<const float2*>(&bias[col]);

    float vx = fmaf(hself.x, sw.x, acc.x) + bv.x;
    float vy = fmaf(hself.y, sw.y, acc.y) + bv.y;

    const float scale = 1.0507009873554805f;
    const float alpha = 1.6732632423543772f;
    vx = vx > 0.0f ? scale * vx : scale * alpha * (expf(vx) - 1.0f);
    vy = vy > 0.0f ? scale * vy : scale * alpha * (expf(vy) - 1.0f);

    *reinterpret_cast<float2*>(&out[(size_t)node * DDIM + col]) = make_float2(vx, vy);
}

extern "C" void kernel_launch(void* const* d_in, const int* in_sizes, int n_in,
                              void* d_out, int out_size)
{
    const float* features = (const float*)d_in[0];
    const float* W        = (const float*)d_in[1];
    const float* bias     = (const float*)d_in[2];
    const float* skipw    = (const float*)d_in[3];
    const float* ew       = (const float*)d_in[4];
    const int*   esrc     = (const int*)d_in[5];
    const int*   edst     = (const int*)d_in[6];
    float* out = (float*)d_out;

    const int n = in_sizes[0] / DDIM;     // 50000
    const int E = in_sizes[4];            // 800000

    // 1. GEMM (+ fused degree histogram)
    gemm_kernel<<<GBLKS, 256>>>(features, W, edst, E, n);

    // 2. single-pass scan -> CSR offsets
    scan_kernel<<<NSB, 256>>>(n);

    // 3. fill CSR edge array (+ reset scan flags)
    fill_kernel<<<(E + 511) / 512, 512>>>(esrc, edst, ew, E);

    // 4. fused gather + skip + bias + SELU (+ reset counts)
    gather_kernel<<<(n + 15) / 16, 512>>>(bias, skipw, out, n);
}

// round 8
// speedup vs baseline: 1.1662x; 1.1662x over previous
#include <cuda_runtime.h>
#include <cuda_fp16.h>
#include <math.h>

#define NMAX 50000
#define EMAX 800000
#define DDIM 64

#define SBLK 1024                          // nodes per scan block
#define NSB ((NMAX + SBLK - 1) / SBLK)     // 49

// scratch (all zero-initialized at module load)
__device__ float  g_h[(size_t)NMAX * DDIM];    // fp32 transformed features (self/skip)
__device__ __half g_hh[(size_t)NMAX * DDIM];   // fp16 copy (neighbor gather)
__device__ int    g_cnt[NMAX];                 // per-node degree (zeroed by gather)
__device__ int    g_off[NMAX];                 // CSR offsets
__device__ int    g_fill[NMAX];                // fill cursors
__device__ unsigned long long g_aggf[NSB];     // packed (flag<<32 | blocksum), reset by fill
__device__ uint2  g_edges[EMAX];               // (src, w-bits) grouped by dst

// ---------------------------------------------------------------------------
// Kernel 1: h = X @ W^T (fp32 + fp16 stores) + fused degree histogram.
// ---------------------------------------------------------------------------
#define XSTR 132
#define WSTR 68
#define GBLKS ((NMAX + 127) / 128)   // 391

__global__ void __launch_bounds__(256) gemm_kernel(
    const float* __restrict__ X, const float* __restrict__ W,
    const int* __restrict__ edst, int E, int n)
{
    __shared__ float sW[DDIM * WSTR];   // sW[d*WSTR + o]
    __shared__ float sX[DDIM * XSTR];   // sX[d*XSTR + r]

    const int tid  = threadIdx.x;
    const int row0 = blockIdx.x * 128;

    // fused histogram: grid-stride, fire-and-forget (g_cnt zero at entry:
    // static init on run 1, re-zeroed by gather_kernel on every run).
    for (int i = blockIdx.x * 256 + tid; i < E; i += GBLKS * 256)
        atomicAdd(&g_cnt[edst[i]], 1);

    #pragma unroll
    for (int i = 0; i < 16; i++) {
        int idx = tid + i * 256;
        int o = idx >> 6, d = idx & 63;
        sW[d * WSTR + o] = W[idx];
    }
    #pragma unroll
    for (int i = 0; i < 32; i++) {
        int idx = tid + i * 256;
        int r = idx >> 6, d = idx & 63;
        int gr = row0 + r;
        sX[d * XSTR + r] = (gr < n) ? X[(size_t)gr * DDIM + d] : 0.0f;
    }
    __syncthreads();

    const int tx = tid & 15;
    const int ty = tid >> 4;
    const int o0 = tx * 4;
    const int r0 = ty * 8;

    float acc[8][4];
    #pragma unroll
    for (int i = 0; i < 8; i++)
        #pragma unroll
        for (int j = 0; j < 4; j++) acc[i][j] = 0.0f;

    #pragma unroll 16
    for (int d = 0; d < DDIM; d++) {
        float4 xa = *reinterpret_cast<const float4*>(&sX[d * XSTR + r0]);
        float4 xb = *reinterpret_cast<const float4*>(&sX[d * XSTR + r0 + 4]);
        float4 wv = *reinterpret_cast<const float4*>(&sW[d * WSTR + o0]);
        float x[8] = {xa.x, xa.y, xa.z, xa.w, xb.x, xb.y, xb.z, xb.w};
        float w[4] = {wv.x, wv.y, wv.z, wv.w};
        #pragma unroll
        for (int i = 0; i < 8; i++)
            #pragma unroll
            for (int j = 0; j < 4; j++)
                acc[i][j] = fmaf(x[i], w[j], acc[i][j]);
    }

    #pragma unroll
    for (int i = 0; i < 8; i++) {
        int gr = row0 + r0 + i;
        if (gr < n) {
            float4 hv = make_float4(acc[i][0], acc[i][1], acc[i][2], acc[i][3]);
            *reinterpret_cast<float4*>(&g_h[(size_t)gr * DDIM + o0]) = hv;
            __half2* dst2 = reinterpret_cast<__half2*>(&g_hh[(size_t)gr * DDIM + o0]);
            dst2[0] = __float22half2_rn(make_float2(hv.x, hv.y));
            dst2[1] = __float22half2_rn(make_float2(hv.z, hv.w));
        }
    }
}

// ---------------------------------------------------------------------------
// Kernel 2: single-pass exclusive scan of g_cnt -> g_off / g_fill.
// ---------------------------------------------------------------------------
__global__ void __launch_bounds__(256) scan_kernel(int n)
{
    __shared__ int sv[256];
    __shared__ int sbase;
    const int b = blockIdx.x, t = threadIdx.x;
    const int base = b * SBLK + t * 4;

    int c[4];
    int s = 0;
    #pragma unroll
    for (int k = 0; k < 4; k++) {
        int i = base + k;
        c[k] = (i < n) ? g_cnt[i] : 0;
        s += c[k];
    }
    sv[t] = s;
    if (t == 0) sbase = 0;
    __syncthreads();
    #pragma unroll
    for (int off = 1; off < 256; off <<= 1) {
        int u = (t >= off) ? sv[t - off] : 0;
        __syncthreads();
        sv[t] += u;
        __syncthreads();
    }

    if (t == 0) {
        unsigned long long v = (1ULL << 32) | (unsigned)sv[255];
        atomicExch(&g_aggf[b], v);
    }
    __syncthreads();

    if (t < b) {
        unsigned long long v;
        do {
            v = *((volatile unsigned long long*)&g_aggf[t]);
        } while (!(v >> 32));
        atomicAdd(&sbase, (int)(unsigned)v);
    }
    __syncthreads();

    int run = sbase + sv[t] - s;   // global exclusive prefix
    #pragma unroll
    for (int k = 0; k < 4; k++) {
        int i = base + k;
        if (i < n) {
            g_off[i]  = run;
            g_fill[i] = run;
            run += c[k];
        }
    }
}

// ---------------------------------------------------------------------------
// Kernel 3: fill CSR edge array; reset scan flags for the next replay.
// ---------------------------------------------------------------------------
__global__ void fill_kernel(const int* __restrict__ src,
                            const int* __restrict__ dst,
                            const float* __restrict__ ew, int E)
{
    int i = blockIdx.x * blockDim.x + threadIdx.x;
    if (i < NSB) g_aggf[i] = 0ULL;
    if (i < E) {
        int d = dst[i];
        int slot = atomicAdd(&g_fill[d], 1);
        g_edges[slot] = make_uint2((unsigned)src[i], __float_as_uint(ew[i]));
    }
}

// ---------------------------------------------------------------------------
// Kernel 4: per-node gather + skip + bias + SELU.
// One warp per node. Lane-parallel edge-meta load + shfl broadcast:
// all gather addresses become register-resident after ONE coalesced load,
// so the ~deg h-row loads issue back-to-back (high MLP, short critical path).
// ---------------------------------------------------------------------------
__global__ void __launch_bounds__(256) gather_kernel(
    const float* __restrict__ bias,
    const float* __restrict__ skipw,
    float* __restrict__ out, int n)
{
    const int lane = threadIdx.x & 31;
    const int node = blockIdx.x * 8 + (threadIdx.x >> 5);
    if (node >= n) return;

    const int start = g_off[node];
    const int deg   = g_cnt[node];
    if (lane == 0) g_cnt[node] = 0;   // restore zero invariant for next run

    const __half2* hh2 = reinterpret_cast<const __half2*>(g_hh);

    float2 acc = make_float2(0.0f, 0.0f);

    for (int base = 0; base < deg; base += 32) {
        const int m = min(deg - base, 32);
        uint2 meta = make_uint2(0u, 0u);
        if (lane < m) meta = __ldg(&g_edges[start + base + lane]);

        const int chunks = (m + 7) >> 3;
        for (int c = 0; c < chunks; c++) {
            #pragma unroll
            for (int j = 0; j < 8; j++) {
                const int k = c * 8 + j;
                unsigned srck = __shfl_sync(0xffffffffu, meta.x, k);
                float    wk   = __shfl_sync(0xffffffffu, __uint_as_float(meta.y), k);
                const bool ok = (k < m);
                srck = ok ? srck : 0u;
                wk   = ok ? wk   : 0.0f;
                float2 hv = __half22float2(__ldg(&hh2[(size_t)srck * 32 + lane]));
                acc.x = fmaf(wk, hv.x, acc.x);
                acc.y = fmaf(wk, hv.y, acc.y);
            }
        }
    }

    const int col = lane * 2;
    const float2 hself = *reinterpret_cast<const float2*>(&g_h[(size_t)node * DDIM + col]);
    const float2 sw = *reinterpret_cast<const float2*>(&skipw[col]);
    const float2 bv = *reinterpret_cast<const float2*>(&bias[col]);

    float vx = fmaf(hself.x, sw.x, acc.x) + bv.x;
    float vy = fmaf(hself.y, sw.y, acc.y) + bv.y;

    const float scale = 1.0507009873554805f;
    const float alpha = 1.6732632423543772f;
    vx = vx > 0.0f ? scale * vx : scale * alpha * (expf(vx) - 1.0f);
    vy = vy > 0.0f ? scale * vy : scale * alpha * (expf(vy) - 1.0f);

    *reinterpret_cast<float2*>(&out[(size_t)node * DDIM + col]) = make_float2(vx, vy);
}

extern "C" void kernel_launch(void* const* d_in, const int* in_sizes, int n_in,
                              void* d_out, int out_size)
{
    const float* features = (const float*)d_in[0];
    const float* W        = (const float*)d_in[1];
    const float* bias     = (const float*)d_in[2];
    const float* skipw    = (const float*)d_in[3];
    const float* ew       = (const float*)d_in[4];
    const int*   esrc     = (const int*)d_in[5];
    const int*   edst     = (const int*)d_in[6];
    float* out = (float*)d_out;

    const int n = in_sizes[0] / DDIM;     // 50000
    const int E = in_sizes[4];            // 800000

    // 1. GEMM (+ fused degree histogram)
    gemm_kernel<<<GBLKS, 256>>>(features, W, edst, E, n);

    // 2. single-pass scan -> CSR offsets
    scan_kernel<<<NSB, 256>>>(n);

    // 3. fill CSR edge array (+ reset scan flags)
    fill_kernel<<<(E + 511) / 512, 512>>>(esrc, edst, ew, E);

    // 4. fused gather + skip + bias + SELU (+ reset counts)
    gather_kernel<<<(n + 7) / 8, 256>>>(bias, skipw, out, n);
}

// round 9
// speedup vs baseline: 1.5965x; 1.3690x over previous
#include <cuda_runtime.h>
#include <cuda_fp16.h>
#include <math.h>

#define NMAX 50000
#define DDIM 64

// fp16 copy of transformed features (gather side of the scatter)
__device__ __half g_hh[(size_t)NMAX * DDIM];

// ---------------------------------------------------------------------------
// Kernel 1: h = X @ W^T ; out = h*skip + bias (fp32) ; g_hh = h (fp16)
// 128 rows x 64 cols per block, 8x4 register tile per thread.
// ---------------------------------------------------------------------------
#define XSTR 132
#define WSTR 68

__global__ void __launch_bounds__(256) gemm_skip_kernel(
    const float* __restrict__ X, const float* __restrict__ W,
    const float* __restrict__ bias, const float* __restrict__ skipw,
    float* __restrict__ out, int n)
{
    __shared__ float sW[DDIM * WSTR];   // sW[d*WSTR + o]
    __shared__ float sX[DDIM * XSTR];   // sX[d*XSTR + r]

    const int tid  = threadIdx.x;
    const int row0 = blockIdx.x * 128;

    #pragma unroll
    for (int i = 0; i < 16; i++) {
        int idx = tid + i * 256;
        int o = idx >> 6, d = idx & 63;
        sW[d * WSTR + o] = W[idx];
    }
    #pragma unroll
    for (int i = 0; i < 32; i++) {
        int idx = tid + i * 256;
        int r = idx >> 6, d = idx & 63;
        int gr = row0 + r;
        sX[d * XSTR + r] = (gr < n) ? X[(size_t)gr * DDIM + d] : 0.0f;
    }
    __syncthreads();

    const int tx = tid & 15;
    const int ty = tid >> 4;
    const int o0 = tx * 4;
    const int r0 = ty * 8;

    float acc[8][4];
    #pragma unroll
    for (int i = 0; i < 8; i++)
        #pragma unroll
        for (int j = 0; j < 4; j++) acc[i][j] = 0.0f;

    #pragma unroll 16
    for (int d = 0; d < DDIM; d++) {
        float4 xa = *reinterpret_cast<const float4*>(&sX[d * XSTR + r0]);
        float4 xb = *reinterpret_cast<const float4*>(&sX[d * XSTR + r0 + 4]);
        float4 wv = *reinterpret_cast<const float4*>(&sW[d * WSTR + o0]);
        float x[8] = {xa.x, xa.y, xa.z, xa.w, xb.x, xb.y, xb.z, xb.w};
        float w[4] = {wv.x, wv.y, wv.z, wv.w};
        #pragma unroll
        for (int i = 0; i < 8; i++)
            #pragma unroll
            for (int j = 0; j < 4; j++)
                acc[i][j] = fmaf(x[i], w[j], acc[i][j]);
    }

    const float4 swv = *reinterpret_cast<const float4*>(&skipw[o0]);
    const float4 bvv = *reinterpret_cast<const float4*>(&bias[o0]);

    #pragma unroll
    for (int i = 0; i < 8; i++) {
        int gr = row0 + r0 + i;
        if (gr < n) {
            float4 hv = make_float4(acc[i][0], acc[i][1], acc[i][2], acc[i][3]);
            // fp16 copy for the scatter's gather side
            __half2* dst2 = reinterpret_cast<__half2*>(&g_hh[(size_t)gr * DDIM + o0]);
            dst2[0] = __float22half2_rn(make_float2(hv.x, hv.y));
            dst2[1] = __float22half2_rn(make_float2(hv.z, hv.w));
            // fp32 accumulator init: h*skip + bias
            float4 ov;
            ov.x = fmaf(hv.x, swv.x, bvv.x);
            ov.y = fmaf(hv.y, swv.y, bvv.y);
            ov.z = fmaf(hv.z, swv.z, bvv.z);
            ov.w = fmaf(hv.w, swv.w, bvv.w);
            *reinterpret_cast<float4*>(&out[(size_t)gr * DDIM + o0]) = ov;
        }
    }
}

// ---------------------------------------------------------------------------
// Kernel 2: edge-parallel scatter: out[dst] += h_fp16[src] * w
// 8 threads per edge; each loads uint4 (8 halves = 16B) and issues 2x red.v4.
// Per edge: 128B gather + 256B atomic + ~12B meta (meta LDGs broadcast-coalesce
// across the 8 lanes of an edge).
// ---------------------------------------------------------------------------
__global__ void __launch_bounds__(256) scatter_kernel(
    const float* __restrict__ ew,
    const int*   __restrict__ src,
    const int*   __restrict__ dst,
    float* __restrict__ out,
    int E)
{
    const int idx = blockIdx.x * 256 + threadIdx.x;
    const int e = idx >> 3;
    if (e >= E) return;
    const int j8 = (idx & 7) * 8;    // half-offset within the 64-wide row

    const int   s = __ldg(src + e);
    const int   d = __ldg(dst + e);
    const float w = __ldg(ew + e);

    const uint4 p = *reinterpret_cast<const uint4*>(&g_hh[(size_t)s * DDIM + j8]);
    float2 f0 = __half22float2(*reinterpret_cast<const __half2*>(&p.x));
    float2 f1 = __half22float2(*reinterpret_cast<const __half2*>(&p.y));
    float2 f2 = __half22float2(*reinterpret_cast<const __half2*>(&p.z));
    float2 f3 = __half22float2(*reinterpret_cast<const __half2*>(&p.w));

    float* o = out + (size_t)d * DDIM + j8;
    asm volatile(
        "red.global.add.v4.f32 [%0], {%1, %2, %3, %4};"
        :: "l"(o), "f"(f0.x * w), "f"(f0.y * w), "f"(f1.x * w), "f"(f1.y * w)
        : "memory");
    asm volatile(
        "red.global.add.v4.f32 [%0], {%1, %2, %3, %4};"
        :: "l"(o + 4), "f"(f2.x * w), "f"(f2.y * w), "f"(f3.x * w), "f"(f3.y * w)
        : "memory");
}

// ---------------------------------------------------------------------------
// Kernel 3: in-place SELU
// ---------------------------------------------------------------------------
__global__ void __launch_bounds__(256) selu_kernel(float* __restrict__ out, int total4)
{
    const float scale = 1.0507009873554805f;
    const float alpha = 1.6732632423543772f;
    int i = blockIdx.x * blockDim.x + threadIdx.x;
    if (i >= total4) return;
    float4 v = reinterpret_cast<float4*>(out)[i];
    v.x = v.x > 0.0f ? scale * v.x : scale * alpha * (expf(v.x) - 1.0f);
    v.y = v.y > 0.0f ? scale * v.y : scale * alpha * (expf(v.y) - 1.0f);
    v.z = v.z > 0.0f ? scale * v.z : scale * alpha * (expf(v.z) - 1.0f);
    v.w = v.w > 0.0f ? scale * v.w : scale * alpha * (expf(v.w) - 1.0f);
    reinterpret_cast<float4*>(out)[i] = v;
}

extern "C" void kernel_launch(void* const* d_in, const int* in_sizes, int n_in,
                              void* d_out, int out_size)
{
    const float* features = (const float*)d_in[0];
    const float* W        = (const float*)d_in[1];
    const float* bias     = (const float*)d_in[2];
    const float* skipw    = (const float*)d_in[3];
    const float* ew       = (const float*)d_in[4];
    const int*   esrc     = (const int*)d_in[5];
    const int*   edst     = (const int*)d_in[6];
    float* out = (float*)d_out;

    const int n = in_sizes[0] / DDIM;     // 50000
    const int E = in_sizes[4];            // 800000

    // 1. GEMM + skip/bias accumulator init + fp16 copy
    gemm_skip_kernel<<<(n + 127) / 128, 256>>>(features, W, bias, skipw, out, n);

    // 2. edge-parallel scatter (8 threads/edge)
    int sblocks = (E * 8 + 255) / 256;
    scatter_kernel<<<sblocks, 256>>>(ew, esrc, edst, out, E);

    // 3. SELU in place
    int total4 = (n * DDIM) / 4;
    selu_kernel<<<(total4 + 255) / 256, 256>>>(out, total4);
}

// round 10
// speedup vs baseline: 2.0548x; 1.2871x over previous
#include <cuda_runtime.h>
#include <cuda_fp16.h>
#include <math.h>

#define NMAX 50000
#define DDIM 64

// fp16 copy of transformed features (gather side of the scatter)
__device__ __half g_hh[(size_t)NMAX * DDIM];

// ---------------------------------------------------------------------------
// Kernel 1: h = X @ W^T ; out = h*skip + bias (fp32) ; g_hh = h (fp16)
// 128 rows x 64 cols per block, 8x4 register tile per thread.
// ---------------------------------------------------------------------------
#define XSTR 132
#define WSTR 68

__global__ void __launch_bounds__(256) gemm_skip_kernel(
    const float* __restrict__ X, const float* __restrict__ W,
    const float* __restrict__ bias, const float* __restrict__ skipw,
    float* __restrict__ out, int n)
{
    __shared__ float sW[DDIM * WSTR];   // sW[d*WSTR + o]
    __shared__ float sX[DDIM * XSTR];   // sX[d*XSTR + r]

    const int tid  = threadIdx.x;
    const int row0 = blockIdx.x * 128;

    #pragma unroll
    for (int i = 0; i < 16; i++) {
        int idx = tid + i * 256;
        int o = idx >> 6, d = idx & 63;
        sW[d * WSTR + o] = W[idx];
    }
    #pragma unroll
    for (int i = 0; i < 32; i++) {
        int idx = tid + i * 256;
        int r = idx >> 6, d = idx & 63;
        int gr = row0 + r;
        sX[d * XSTR + r] = (gr < n) ? X[(size_t)gr * DDIM + d] : 0.0f;
    }
    __syncthreads();

    const int tx = tid & 15;
    const int ty = tid >> 4;
    const int o0 = tx * 4;
    const int r0 = ty * 8;

    float acc[8][4];
    #pragma unroll
    for (int i = 0; i < 8; i++)
        #pragma unroll
        for (int j = 0; j < 4; j++) acc[i][j] = 0.0f;

    #pragma unroll 16
    for (int d = 0; d < DDIM; d++) {
        float4 xa = *reinterpret_cast<const float4*>(&sX[d * XSTR + r0]);
        float4 xb = *reinterpret_cast<const float4*>(&sX[d * XSTR + r0 + 4]);
        float4 wv = *reinterpret_cast<const float4*>(&sW[d * WSTR + o0]);
        float x[8] = {xa.x, xa.y, xa.z, xa.w, xb.x, xb.y, xb.z, xb.w};
        float w[4] = {wv.x, wv.y, wv.z, wv.w};
        #pragma unroll
        for (int i = 0; i < 8; i++)
            #pragma unroll
            for (int j = 0; j < 4; j++)
                acc[i][j] = fmaf(x[i], w[j], acc[i][j]);
    }

    const float4 swv = *reinterpret_cast<const float4*>(&skipw[o0]);
    const float4 bvv = *reinterpret_cast<const float4*>(&bias[o0]);

    #pragma unroll
    for (int i = 0; i < 8; i++) {
        int gr = row0 + r0 + i;
        if (gr < n) {
            float4 hv = make_float4(acc[i][0], acc[i][1], acc[i][2], acc[i][3]);
            __half2* dst2 = reinterpret_cast<__half2*>(&g_hh[(size_t)gr * DDIM + o0]);
            dst2[0] = __float22half2_rn(make_float2(hv.x, hv.y));
            dst2[1] = __float22half2_rn(make_float2(hv.z, hv.w));
            float4 ov;
            ov.x = fmaf(hv.x, swv.x, bvv.x);
            ov.y = fmaf(hv.y, swv.y, bvv.y);
            ov.z = fmaf(hv.z, swv.z, bvv.z);
            ov.w = fmaf(hv.w, swv.w, bvv.w);
            *reinterpret_cast<float4*>(&out[(size_t)gr * DDIM + o0]) = ov;
        }
    }
}

// ---------------------------------------------------------------------------
// Kernel 2: out[dst] += h_fp16[src] * w   via red.global.add.v4.f32
// R2 structure: edge metadata staged in smem (coalesced once), 16 lanes/edge,
// one red.v4 per lane. Only change vs R2: gather reads fp16 (uint2 = 4 halves).
// ---------------------------------------------------------------------------
#define EPB 256

__global__ void __launch_bounds__(256) scatter_kernel(
    const float* __restrict__ ew,
    const int*   __restrict__ src,
    const int*   __restrict__ dst,
    float* __restrict__ out,
    int E)
{
    __shared__ int   es[EPB];
    __shared__ int   ed[EPB];
    __shared__ float ewt[EPB];

    const int tid  = threadIdx.x;
    const int base = blockIdx.x * EPB;

    int ge = base + tid;
    if (ge < E) {
        es[tid]  = src[ge];
        ed[tid]  = dst[ge];
        ewt[tid] = ew[ge];
    }
    __syncthreads();

    const int lane4 = (tid & 15) << 2;   // 0,4,...,60 (4 floats per lane)
    const int esub  = tid >> 4;          // 0..15

    #pragma unroll
    for (int p = 0; p < 16; p++) {
        int e = p * 16 + esub;
        if (base + e >= E) break;
        int   s = es[e];
        int   d = ed[e];
        float w = ewt[e];

        // 4 halves = 8 bytes
        const uint2 pk = *reinterpret_cast<const uint2*>(
            &g_hh[(size_t)s * DDIM + lane4]);
        float2 f0 = __half22float2(*reinterpret_cast<const __half2*>(&pk.x));
        float2 f1 = __half22float2(*reinterpret_cast<const __half2*>(&pk.y));

        float* o = out + (size_t)d * DDIM + lane4;
        asm volatile(
            "red.global.add.v4.f32 [%0], {%1, %2, %3, %4};"
            :: "l"(o), "f"(f0.x * w), "f"(f0.y * w), "f"(f1.x * w), "f"(f1.y * w)
            : "memory");
    }
}

// ---------------------------------------------------------------------------
// Kernel 3: in-place SELU
// ---------------------------------------------------------------------------
__global__ void __launch_bounds__(256) selu_kernel(float* __restrict__ out, int total4)
{
    const float scale = 1.0507009873554805f;
    const float alpha = 1.6732632423543772f;
    int i = blockIdx.x * blockDim.x + threadIdx.x;
    if (i >= total4) return;
    float4 v = reinterpret_cast<float4*>(out)[i];
    v.x = v.x > 0.0f ? scale * v.x : scale * alpha * (expf(v.x) - 1.0f);
    v.y = v.y > 0.0f ? scale * v.y : scale * alpha * (expf(v.y) - 1.0f);
    v.z = v.z > 0.0f ? scale * v.z : scale * alpha * (expf(v.z) - 1.0f);
    v.w = v.w > 0.0f ? scale * v.w : scale * alpha * (expf(v.w) - 1.0f);
    reinterpret_cast<float4*>(out)[i] = v;
}

extern "C" void kernel_launch(void* const* d_in, const int* in_sizes, int n_in,
                              void* d_out, int out_size)
{
    const float* features = (const float*)d_in[0];
    const float* W        = (const float*)d_in[1];
    const float* bias     = (const float*)d_in[2];
    const float* skipw    = (const float*)d_in[3];
    const float* ew       = (const float*)d_in[4];
    const int*   esrc     = (const int*)d_in[5];
    const int*   edst     = (const int*)d_in[6];
    float* out = (float*)d_out;

    const int n = in_sizes[0] / DDIM;     // 50000
    const int E = in_sizes[4];            // 800000

    // 1. GEMM + skip/bias accumulator init + fp16 copy
    gemm_skip_kernel<<<(n + 127) / 128, 256>>>(features, W, bias, skipw, out, n);

    // 2. edge-parallel scatter (16 threads/edge, staged meta)
    int sblocks = (E + EPB - 1) / EPB;
    scatter_kernel<<<sblocks, 256>>>(ew, esrc, edst, out, E);

    // 3. SELU in place
    int total4 = (n * DDIM) / 4;
    selu_kernel<<<(total4 + 255) / 256, 256>>>(out, total4);
}